// round 1
// baseline (speedup 1.0000x reference)
#include <cuda_runtime.h>
#include <math.h>
#include <stdint.h>

// ---------------- problem constants ----------------
#define BB   8
#define LL   1024
#define DMD  256
#define NLY  4
#define EDD  512
#define NSS  16
#define DCC  4
#define RKK  16
#define CDD  64
#define QQ   2
#define BL   (BB*LL)          // 8192 rows
#define NCH  16               // scan chunks
#define CHL  (LL/NCH)         // 64 steps per chunk

// ---------------- scratch (static device globals; no allocs allowed) ----------------
__device__ __align__(256) float g_x [BL*DMD];
__device__ __align__(256) float g_xn[BL*DMD];
__device__ __align__(256) float g_xz[BL*2*EDD];
__device__ __align__(256) float g_xs[BL*EDD];
__device__ __align__(256) float g_r [BL*EDD];
__device__ __align__(256) float g_p [BL*EDD];
__device__ __align__(256) float g_y [BL*EDD];
__device__ __align__(256) float g_xd[BL*48];
__device__ __align__(256) float g_cond[BB*CDD];
__device__ __align__(256) float g_ss[NLY*BB*2*DMD];
__device__ __align__(256) float g_aP[BB*NCH*NSS*EDD];
__device__ __align__(256) float g_bL[BB*NCH*NSS*EDD];
__device__ __align__(256) float g_hI[BB*NCH*NSS*EDD];

// ---------------- embed: x = shift(tok_embed[tokens]) + pos_embed ----------------
__global__ void k_embed(const int* __restrict__ tokens,
                        const float* __restrict__ tok_embed,
                        const float* __restrict__ pos_embed)
{
    int idx = blockIdx.x * 256 + threadIdx.x;
    if (idx >= BL*DMD) return;
    int d  = idx % DMD;
    int bl = idx / DMD;
    int l  = bl % LL;
    int b  = bl / LL;
    float v = pos_embed[l*DMD + d];
    if (l > 0) {
        int tok = tokens[b*LL + l - 1];
        v += tok_embed[tok*DMD + d];
    }
    g_x[idx] = v;
}

// ---------------- conditioning: cond = gelu(T*tw1+tb1)@tw2 + tb2 (tiny) ----------------
__global__ void k_cond(const float* __restrict__ T,  const float* __restrict__ tw1,
                       const float* __restrict__ tb1,const float* __restrict__ tw2,
                       const float* __restrict__ tb2)
{
    __shared__ float hs[BB*CDD];
    int tid = threadIdx.x;            // 512 threads
    int b = tid / CDD, c = tid % CDD;
    float u = T[b]*tw1[c] + tb1[c];
    // exact gelu
    float g = 0.5f*u*(1.0f + erff(u*0.70710678118654752440f));
    hs[b*CDD + c] = g;
    __syncthreads();
    float acc = tb2[c];
    #pragma unroll 8
    for (int k = 0; k < CDD; k++) acc += hs[b*CDD + k]*tw2[k*CDD + c];
    g_cond[b*CDD + c] = acc;
}

// ---------------- per-layer modulation vectors: ss = cond @ apw + apb ----------------
__global__ void k_ss(const float* __restrict__ apw, const float* __restrict__ apb)
{
    int idx = blockIdx.x*256 + threadIdx.x;     // NLY*BB*2DM = 16384
    if (idx >= NLY*BB*2*DMD) return;
    int j  = idx % (2*DMD);
    int ib = idx / (2*DMD);
    int b  = ib % BB;
    int i  = ib / BB;
    float acc = apb[i*2*DMD + j];
    #pragma unroll 8
    for (int c = 0; c < CDD; c++)
        acc += g_cond[b*CDD + c] * apw[((size_t)i*CDD + c)*2*DMD + j];
    g_ss[((size_t)i*BB + b)*2*DMD + j] = acc;
}

// ---------------- LayerNorm (+ optional AdaLN modulation) ----------------
// one block (256 thr) per row; ss==nullptr -> plain LN (final)
__global__ void k_ln(const float* __restrict__ x, const float* __restrict__ gam,
                     const float* __restrict__ bet, const float* __restrict__ ss,
                     float* __restrict__ out)
{
    int row = blockIdx.x;
    int tid = threadIdx.x;
    float v = x[(size_t)row*DMD + tid];
    __shared__ float red[8];
    float s = v;
    #pragma unroll
    for (int o = 16; o; o >>= 1) s += __shfl_xor_sync(0xffffffffu, s, o);
    if ((tid & 31) == 0) red[tid >> 5] = s;
    __syncthreads();
    float tot = red[0]+red[1]+red[2]+red[3]+red[4]+red[5]+red[6]+red[7];
    float mean = tot * (1.0f/DMD);
    float d = v - mean;
    float s2 = d*d;
    __syncthreads();
    #pragma unroll
    for (int o = 16; o; o >>= 1) s2 += __shfl_xor_sync(0xffffffffu, s2, o);
    if ((tid & 31) == 0) red[tid >> 5] = s2;
    __syncthreads();
    float var = (red[0]+red[1]+red[2]+red[3]+red[4]+red[5]+red[6]+red[7]) * (1.0f/DMD);
    float o_ = d * rsqrtf(var + 1e-5f) * gam[tid] + bet[tid];
    if (ss) {
        int b = row / LL;
        float sc = ss[(size_t)b*2*DMD + tid];
        float sh = ss[(size_t)b*2*DMD + DMD + tid];
        o_ = fmaf(sc, o_, o_) + sh;        // (1+sc)*o + sh
    }
    out[(size_t)row*DMD + tid] = o_;
}

// ---------------- generic fp32 tiled GEMM: C[M,N] (+)= A[M,K] @ W[K,N] ----------------
template<int BM, int BN, int BK, int TM, int TN>
__global__ void gemm_tiled(const float* __restrict__ A, const float* __restrict__ W,
                           float* __restrict__ C, int M, int N, int K, int accum)
{
    constexpr int NTHR = (BM/TM)*(BN/TN);
    constexpr int PA = BM + 4;
    __shared__ float As[BK][PA];
    __shared__ float Ws[BK][BN];
    const int tid  = threadIdx.x;
    const int tx   = tid % (BN/TN);
    const int ty   = tid / (BN/TN);
    const int row0 = blockIdx.y * BM;
    const int col0 = blockIdx.x * BN;

    float acc[TM][TN];
    #pragma unroll
    for (int i = 0; i < TM; i++)
        #pragma unroll
        for (int j = 0; j < TN; j++) acc[i][j] = 0.0f;

    for (int k0 = 0; k0 < K; k0 += BK) {
        // A tile (BM x BK), float4 along K, stored transposed into As[k][m]
        #pragma unroll
        for (int f = tid; f < BM*(BK/4); f += NTHR) {
            int m  = f / (BK/4);
            int kg = (f % (BK/4)) * 4;
            float4 v = *reinterpret_cast<const float4*>(A + (size_t)(row0+m)*K + k0 + kg);
            As[kg+0][m] = v.x; As[kg+1][m] = v.y; As[kg+2][m] = v.z; As[kg+3][m] = v.w;
        }
        // W tile (BK x BN), guarded on N
        #pragma unroll
        for (int f = tid; f < BK*(BN/4); f += NTHR) {
            int kr = f / (BN/4);
            int ng = (f % (BN/4)) * 4;
            int col = col0 + ng;
            float4 v;
            if (col + 3 < N) {
                v = *reinterpret_cast<const float4*>(W + (size_t)(k0+kr)*N + col);
            } else {
                v.x = (col+0 < N) ? W[(size_t)(k0+kr)*N + col+0] : 0.0f;
                v.y = (col+1 < N) ? W[(size_t)(k0+kr)*N + col+1] : 0.0f;
                v.z = (col+2 < N) ? W[(size_t)(k0+kr)*N + col+2] : 0.0f;
                v.w = (col+3 < N) ? W[(size_t)(k0+kr)*N + col+3] : 0.0f;
            }
            *reinterpret_cast<float4*>(&Ws[kr][ng]) = v;
        }
        __syncthreads();
        #pragma unroll
        for (int k = 0; k < BK; k++) {
            float ra[TM], rw[TN];
            #pragma unroll
            for (int i = 0; i < TM; i++) ra[i] = As[k][ty*TM + i];
            #pragma unroll
            for (int j = 0; j < TN; j++) rw[j] = Ws[k][tx*TN + j];
            #pragma unroll
            for (int i = 0; i < TM; i++)
                #pragma unroll
                for (int j = 0; j < TN; j++)
                    acc[i][j] = fmaf(ra[i], rw[j], acc[i][j]);
        }
        __syncthreads();
    }
    #pragma unroll
    for (int i = 0; i < TM; i++) {
        int rr = row0 + ty*TM + i;
        if (rr >= M) continue;
        #pragma unroll
        for (int j = 0; j < TN; j++) {
            int cc = col0 + tx*TN + j;
            if (cc >= N) continue;
            float v = acc[i][j];
            size_t idx = (size_t)rr*N + cc;
            if (accum) v += C[idx];
            C[idx] = v;
        }
    }
}

// ---------------- depthwise causal conv (DC=4) + bias + silu ----------------
__global__ void k_conv(const float* __restrict__ w, const float* __restrict__ cb)
{
    int idx = blockIdx.x*256 + threadIdx.x;         // BL*ED
    if (idx >= BL*EDD) return;
    int e  = idx % EDD;
    int bl = idx / EDD;
    int l  = bl % LL;
    float4 wv = *reinterpret_cast<const float4*>(w + (size_t)e*DCC);
    const float* base = g_xz + (size_t)bl*(2*EDD) + e;   // xs_raw = xz[..., :ED]
    float acc = cb[e] + wv.w * base[0];
    if (l >= 1) acc += wv.z * base[-1*(2*EDD)];
    if (l >= 2) acc += wv.y * base[-2*(2*EDD)];
    if (l >= 3) acc += wv.x * base[-3*(2*EDD)];
    float sg = 1.0f/(1.0f + __expf(-acc));
    g_xs[idx] = acc * sg;                                // silu
}

// ---------------- delta: raw = xd[:,:16]@dt_w + dt_b; r=exp(-softplus), p=softplus*xs ----------------
__global__ void k_dlt(const float* __restrict__ dtw, const float* __restrict__ dtb)
{
    int idx = blockIdx.x*256 + threadIdx.x;         // BL*ED
    if (idx >= BL*EDD) return;
    int e  = idx % EDD;
    int bl = idx / EDD;
    const float* xr = g_xd + (size_t)bl*48;
    float acc = dtb[e];
    #pragma unroll
    for (int k = 0; k < RKK; k++)
        acc = fmaf(xr[k], dtw[(size_t)k*EDD + e], acc);
    float dlt, rr;
    if (acc > 15.0f) {                 // softplus(x) ~= x
        dlt = acc;
        rr  = __expf(-acc);
    } else {
        float ex = __expf(acc);
        rr  = 1.0f/(1.0f + ex);        // exp(-softplus(x)) = sigmoid(-x)
        dlt = log1pf(ex);
    }
    g_r[idx] = rr;
    g_p[idx] = dlt * g_xs[idx];
}

// ---------------- scan pass 1: per-chunk summaries (aP, bLoc) ----------------
__global__ void k_scan1(const float* __restrict__ Alog)
{
    int e = blockIdx.x*128 + threadIdx.x;
    int c = blockIdx.y, b = blockIdx.z;
    __shared__ float Bsh[CHL][NSS];
    for (int f = threadIdx.x; f < CHL*NSS; f += 128) {
        int t = f / NSS, n = f % NSS;
        Bsh[t][n] = g_xd[((size_t)(b*LL + c*CHL + t))*48 + RKK + n];
    }
    float a[NSS];
    bool fast = true;
    #pragma unroll
    for (int n = 0; n < NSS; n++) {
        a[n] = expf(Alog[(size_t)e*NSS + n]);
        if (fabsf(a[n] - (float)(n+1)) > 1e-4f*(float)(n+1)) fast = false;
    }
    __syncthreads();
    float h[NSS];
    #pragma unroll
    for (int n = 0; n < NSS; n++) h[n] = 0.0f;
    const float* rp = g_r + ((size_t)(b*LL + c*CHL))*EDD + e;
    const float* pp = g_p + ((size_t)(b*LL + c*CHL))*EDD + e;
    size_t ob = ((size_t)(b*NCH + c)*NSS)*EDD + e;
    if (fast) {
        float rprod = 1.0f;
        for (int t = 0; t < CHL; t++) {
            float rv = rp[(size_t)t*EDD], pv = pp[(size_t)t*EDD];
            float rn = 1.0f;
            #pragma unroll
            for (int n = 0; n < NSS; n++) {
                rn *= rv;                               // rv^(n+1)
                h[n] = fmaf(rn, h[n], pv*Bsh[t][n]);
            }
            rprod *= rv;
        }
        float rpn = 1.0f;
        #pragma unroll
        for (int n = 0; n < NSS; n++) {
            rpn *= rprod;
            g_aP[ob + (size_t)n*EDD] = rpn;
            g_bL[ob + (size_t)n*EDD] = h[n];
        }
    } else {
        float msum = 0.0f;
        for (int t = 0; t < CHL; t++) {
            float rv = rp[(size_t)t*EDD], pv = pp[(size_t)t*EDD];
            float ml = __logf(rv);                       // = -dlt
            msum += ml;
            #pragma unroll
            for (int n = 0; n < NSS; n++) {
                float dA = __expf(a[n]*ml);
                h[n] = fmaf(dA, h[n], pv*Bsh[t][n]);
            }
        }
        #pragma unroll
        for (int n = 0; n < NSS; n++) {
            g_aP[ob + (size_t)n*EDD] = __expf(a[n]*msum);
            g_bL[ob + (size_t)n*EDD] = h[n];
        }
    }
}

// ---------------- scan pass 2: sequential combine over chunks -> initial states ----------------
__global__ void k_scan2()
{
    int idx = blockIdx.x*256 + threadIdx.x;   // BB*ED
    if (idx >= BB*EDD) return;
    int e = idx % EDD, b = idx / EDD;
    float h[NSS];
    #pragma unroll
    for (int n = 0; n < NSS; n++) h[n] = 0.0f;
    for (int c = 0; c < NCH; c++) {
        size_t ob = ((size_t)(b*NCH + c)*NSS)*EDD + e;
        #pragma unroll
        for (int n = 0; n < NSS; n++) {
            g_hI[ob + (size_t)n*EDD] = h[n];
            h[n] = fmaf(g_aP[ob + (size_t)n*EDD], h[n], g_bL[ob + (size_t)n*EDD]);
        }
    }
}

// ---------------- scan pass 3: replay with init state, emit y = (h.C + Dp*xs)*silu(z) ----------------
__global__ void k_scan3(const float* __restrict__ Alog, const float* __restrict__ Dp)
{
    int e = blockIdx.x*128 + threadIdx.x;
    int c = blockIdx.y, b = blockIdx.z;
    __shared__ float Bsh[CHL][NSS];
    __shared__ float Csh[CHL][NSS];
    for (int f = threadIdx.x; f < CHL*NSS; f += 128) {
        int t = f / NSS, n = f % NSS;
        size_t rbase = ((size_t)(b*LL + c*CHL + t))*48;
        Bsh[t][n] = g_xd[rbase + RKK + n];
        Csh[t][n] = g_xd[rbase + RKK + NSS + n];
    }
    float a[NSS];
    bool fast = true;
    #pragma unroll
    for (int n = 0; n < NSS; n++) {
        a[n] = expf(Alog[(size_t)e*NSS + n]);
        if (fabsf(a[n] - (float)(n+1)) > 1e-4f*(float)(n+1)) fast = false;
    }
    __syncthreads();
    float h[NSS];
    size_t ob = ((size_t)(b*NCH + c)*NSS)*EDD + e;
    #pragma unroll
    for (int n = 0; n < NSS; n++) h[n] = g_hI[ob + (size_t)n*EDD];
    float dp = Dp[e];
    const float* rp = g_r  + ((size_t)(b*LL + c*CHL))*EDD + e;
    const float* pp = g_p  + ((size_t)(b*LL + c*CHL))*EDD + e;
    const float* xp = g_xs + ((size_t)(b*LL + c*CHL))*EDD + e;
    const float* zp = g_xz + ((size_t)(b*LL + c*CHL))*(2*EDD) + EDD + e;
    float*       yp = g_y  + ((size_t)(b*LL + c*CHL))*EDD + e;
    if (fast) {
        for (int t = 0; t < CHL; t++) {
            float rv = rp[(size_t)t*EDD], pv = pp[(size_t)t*EDD];
            float xv = xp[(size_t)t*EDD], zv = zp[(size_t)t*(2*EDD)];
            float yacc = dp * xv;
            float rn = 1.0f;
            #pragma unroll
            for (int n = 0; n < NSS; n++) {
                rn *= rv;
                h[n]  = fmaf(rn, h[n], pv*Bsh[t][n]);
                yacc  = fmaf(h[n], Csh[t][n], yacc);
            }
            float sg = 1.0f/(1.0f + __expf(-zv));
            yp[(size_t)t*EDD] = yacc * (zv * sg);
        }
    } else {
        for (int t = 0; t < CHL; t++) {
            float rv = rp[(size_t)t*EDD], pv = pp[(size_t)t*EDD];
            float xv = xp[(size_t)t*EDD], zv = zp[(size_t)t*(2*EDD)];
            float ml = __logf(rv);
            float yacc = dp * xv;
            #pragma unroll
            for (int n = 0; n < NSS; n++) {
                float dA = __expf(a[n]*ml);
                h[n]  = fmaf(dA, h[n], pv*Bsh[t][n]);
                yacc  = fmaf(h[n], Csh[t][n], yacc);
            }
            float sg = 1.0f/(1.0f + __expf(-zv));
            yp[(size_t)t*EDD] = yacc * (zv * sg);
        }
    }
}

// ---------------- head: out = LN(x)@hw + hb ----------------
__global__ void k_head(const float* __restrict__ hw, const float* __restrict__ hb,
                       float* __restrict__ out)
{
    int row = blockIdx.x, tid = threadIdx.x;   // 256 thr
    float v = g_xn[(size_t)row*DMD + tid];
    float p0 = v * hw[tid*QQ + 0];
    float p1 = v * hw[tid*QQ + 1];
    __shared__ float r0[8], r1[8];
    #pragma unroll
    for (int o = 16; o; o >>= 1) {
        p0 += __shfl_xor_sync(0xffffffffu, p0, o);
        p1 += __shfl_xor_sync(0xffffffffu, p1, o);
    }
    if ((tid & 31) == 0) { r0[tid>>5] = p0; r1[tid>>5] = p1; }
    __syncthreads();
    if (tid == 0) {
        float s0 = r0[0]+r0[1]+r0[2]+r0[3]+r0[4]+r0[5]+r0[6]+r0[7];
        float s1 = r1[0]+r1[1]+r1[2]+r1[3]+r1[4]+r1[5]+r1[6]+r1[7];
        out[(size_t)row*QQ + 0] = s0 + hb[0];
        out[(size_t)row*QQ + 1] = s1 + hb[1];
    }
}

// ---------------- launcher ----------------
extern "C" void kernel_launch(void* const* d_in, const int* in_sizes, int n_in,
                              void* d_out, int out_size)
{
    const int*   tokens    = (const int*)  d_in[0];
    const float* T         = (const float*)d_in[1];
    const float* tok_embed = (const float*)d_in[2];
    const float* pos_embed = (const float*)d_in[3];
    const float* tw1       = (const float*)d_in[4];
    const float* tb1       = (const float*)d_in[5];
    const float* tw2       = (const float*)d_in[6];
    const float* tb2       = (const float*)d_in[7];
    const float* ag        = (const float*)d_in[8];
    const float* ab        = (const float*)d_in[9];
    const float* apw       = (const float*)d_in[10];
    const float* apb       = (const float*)d_in[11];
    const float* in_w      = (const float*)d_in[12];
    const float* conv_w    = (const float*)d_in[13];
    const float* conv_b    = (const float*)d_in[14];
    const float* xp_w      = (const float*)d_in[15];
    const float* dt_w      = (const float*)d_in[16];
    const float* dt_b      = (const float*)d_in[17];
    const float* A_log     = (const float*)d_in[18];
    const float* Dp        = (const float*)d_in[19];
    const float* out_w     = (const float*)d_in[20];
    const float* fg        = (const float*)d_in[21];
    const float* fb        = (const float*)d_in[22];
    const float* hw        = (const float*)d_in[23];
    const float* hb        = (const float*)d_in[24];
    float* out = (float*)d_out;

    float *px, *pxn, *pxz, *pxs, *py, *pxd, *pss;
    cudaGetSymbolAddress((void**)&px,  g_x);
    cudaGetSymbolAddress((void**)&pxn, g_xn);
    cudaGetSymbolAddress((void**)&pxz, g_xz);
    cudaGetSymbolAddress((void**)&pxs, g_xs);
    cudaGetSymbolAddress((void**)&py,  g_y);
    cudaGetSymbolAddress((void**)&pxd, g_xd);
    cudaGetSymbolAddress((void**)&pss, g_ss);

    k_embed<<<(BL*DMD + 255)/256, 256>>>(tokens, tok_embed, pos_embed);
    k_cond<<<1, BB*CDD>>>(T, tw1, tb1, tw2, tb2);
    k_ss<<<(NLY*BB*2*DMD + 255)/256, 256>>>(apw, apb);

    for (int i = 0; i < NLY; i++) {
        // AdaLN
        k_ln<<<BL, DMD>>>(px, ag + (size_t)i*DMD, ab + (size_t)i*DMD,
                          pss + (size_t)i*BB*2*DMD, pxn);
        // xz = xn @ in_w[i]   (8192 x 1024, K=256)
        gemm_tiled<128,64,16,8,4><<<dim3(2*EDD/64, BL/128), 256>>>(
            pxn, in_w + (size_t)i*DMD*2*EDD, pxz, BL, 2*EDD, DMD, 0);
        // causal depthwise conv + silu
        k_conv<<<(BL*EDD + 255)/256, 256>>>(conv_w + (size_t)i*EDD*DCC,
                                            conv_b + (size_t)i*EDD);
        // xd = xs @ xp_w[i]   (8192 x 48, K=512)
        gemm_tiled<64,64,16,4,4><<<dim3(1, BL/64), 256>>>(
            pxs, xp_w + (size_t)i*EDD*(RKK+2*NSS), pxd, BL, RKK+2*NSS, EDD, 0);
        // delta -> r, p
        k_dlt<<<(BL*EDD + 255)/256, 256>>>(dt_w + (size_t)i*RKK*EDD,
                                           dt_b + (size_t)i*EDD);
        // chunked selective scan
        k_scan1<<<dim3(EDD/128, NCH, BB), 128>>>(A_log + (size_t)i*EDD*NSS);
        k_scan2<<<(BB*EDD + 255)/256, 256>>>();
        k_scan3<<<dim3(EDD/128, NCH, BB), 128>>>(A_log + (size_t)i*EDD*NSS,
                                                 Dp + (size_t)i*EDD);
        // x += y @ out_w[i]   (8192 x 256, K=512), accumulate
        gemm_tiled<128,64,16,8,4><<<dim3(DMD/64, BL/128), 256>>>(
            py, out_w + (size_t)i*EDD*DMD, px, BL, DMD, EDD, 1);
    }

    // final LN + head
    k_ln<<<BL, DMD>>>(px, fg, fb, nullptr, pxn);
    k_head<<<BL, 256>>>(hw, hb, out);
}

// round 4
// speedup vs baseline: 1.1335x; 1.1335x over previous
#include <cuda_runtime.h>
#include <mma.h>
#include <math.h>
#include <stdint.h>

using namespace nvcuda;

// ---------------- problem constants ----------------
#define BB   8
#define LL   1024
#define DMD  256
#define NLY  4
#define EDD  512
#define NSS  16
#define DCC  4
#define RKK  16
#define CDD  64
#define QQ   2
#define BL   (BB*LL)          // 8192 rows
#define NCH  16               // scan chunks
#define CHL  (LL/NCH)         // 64 steps per chunk

// ---------------- scratch (static device globals; no allocs allowed) ----------------
__device__ __align__(256) float g_x [BL*DMD];
__device__ __align__(256) float g_xn[BL*DMD];
__device__ __align__(256) float g_xz[BL*2*EDD];
__device__ __align__(256) float g_xs[BL*EDD];
__device__ __align__(256) float g_r [BL*EDD];
__device__ __align__(256) float g_p [BL*EDD];
__device__ __align__(256) float g_y [BL*EDD];
__device__ __align__(256) float g_xd[BL*48];
__device__ __align__(256) float g_cond[BB*CDD];
__device__ __align__(256) float g_ss[NLY*BB*2*DMD];
__device__ __align__(256) float g_aP[BB*NCH*NSS*EDD];
__device__ __align__(256) float g_bL[BB*NCH*NSS*EDD];
__device__ __align__(256) float g_hI[BB*NCH*NSS*EDD];

// ---------------- embed: x = shift(tok_embed[tokens]) + pos_embed ----------------
__global__ void k_embed(const int* __restrict__ tokens,
                        const float* __restrict__ tok_embed,
                        const float* __restrict__ pos_embed)
{
    int idx = blockIdx.x * 256 + threadIdx.x;
    if (idx >= BL*DMD) return;
    int d  = idx % DMD;
    int bl = idx / DMD;
    int l  = bl % LL;
    int b  = bl / LL;
    float v = pos_embed[l*DMD + d];
    if (l > 0) {
        int tok = tokens[b*LL + l - 1];
        v += tok_embed[tok*DMD + d];
    }
    g_x[idx] = v;
}

// ---------------- conditioning: cond = gelu(T*tw1+tb1)@tw2 + tb2 (tiny) ----------------
__global__ void k_cond(const float* __restrict__ T,  const float* __restrict__ tw1,
                       const float* __restrict__ tb1,const float* __restrict__ tw2,
                       const float* __restrict__ tb2)
{
    __shared__ float hs[BB*CDD];
    int tid = threadIdx.x;            // 512 threads
    int b = tid / CDD, c = tid % CDD;
    float u = T[b]*tw1[c] + tb1[c];
    float g = 0.5f*u*(1.0f + erff(u*0.70710678118654752440f));
    hs[b*CDD + c] = g;
    __syncthreads();
    float acc = tb2[c];
    #pragma unroll 8
    for (int k = 0; k < CDD; k++) acc += hs[b*CDD + k]*tw2[k*CDD + c];
    g_cond[b*CDD + c] = acc;
}

// ---------------- per-layer modulation vectors: ss = cond @ apw + apb ----------------
__global__ void k_ss(const float* __restrict__ apw, const float* __restrict__ apb)
{
    int idx = blockIdx.x*256 + threadIdx.x;     // NLY*BB*2DM = 16384
    if (idx >= NLY*BB*2*DMD) return;
    int j  = idx % (2*DMD);
    int ib = idx / (2*DMD);
    int b  = ib % BB;
    int i  = ib / BB;
    float acc = apb[i*2*DMD + j];
    #pragma unroll 8
    for (int c = 0; c < CDD; c++)
        acc += g_cond[b*CDD + c] * apw[((size_t)i*CDD + c)*2*DMD + j];
    g_ss[((size_t)i*BB + b)*2*DMD + j] = acc;
}

// ---------------- LayerNorm (+ optional AdaLN modulation), one-pass reduction ----------------
__global__ void k_ln(const float* __restrict__ x, const float* __restrict__ gam,
                     const float* __restrict__ bet, const float* __restrict__ ss,
                     float* __restrict__ out)
{
    int row = blockIdx.x;
    int tid = threadIdx.x;
    float v = x[(size_t)row*DMD + tid];
    __shared__ float red1[8], red2[8];
    float s  = v;
    float s2 = v*v;
    #pragma unroll
    for (int o = 16; o; o >>= 1) {
        s  += __shfl_xor_sync(0xffffffffu, s,  o);
        s2 += __shfl_xor_sync(0xffffffffu, s2, o);
    }
    if ((tid & 31) == 0) { red1[tid >> 5] = s; red2[tid >> 5] = s2; }
    __syncthreads();
    float tot  = red1[0]+red1[1]+red1[2]+red1[3]+red1[4]+red1[5]+red1[6]+red1[7];
    float tot2 = red2[0]+red2[1]+red2[2]+red2[3]+red2[4]+red2[5]+red2[6]+red2[7];
    float mean = tot * (1.0f/DMD);
    float var  = tot2 * (1.0f/DMD) - mean*mean;
    float o_ = (v - mean) * rsqrtf(var + 1e-5f) * gam[tid] + bet[tid];
    if (ss) {
        int b = row / LL;
        float sc = ss[(size_t)b*2*DMD + tid];
        float sh = ss[(size_t)b*2*DMD + DMD + tid];
        o_ = fmaf(sc, o_, o_) + sh;        // (1+sc)*o + sh
    }
    out[(size_t)row*DMD + tid] = o_;
}

// ---------------- TF32 tensor-core GEMM: C[M,N] (+)= A[M,K] @ W[K,N] ----------------
// BM x BN block tile, BK k-tile, 32x32 warp tiles via wmma m16n16k8 tf32.
template<int BM, int BN, int BK>
__global__ void __launch_bounds__((BM/32)*(BN/32)*32)
gemm_tf32(const float* __restrict__ A, const float* __restrict__ W,
          float* __restrict__ C, int M, int N, int K, int accum)
{
    constexpr int WROWS = BM/32, WCOLS = BN/32;
    constexpr int NW  = WROWS*WCOLS;
    constexpr int NT  = NW*32;
    constexpr int LDA = BK + 4;
    constexpr int LDB = BN + 4;
    constexpr int LDE = BN + 4;
    static_assert(BM*LDA + BK*LDB <= BM*LDE, "smem reuse");

    __shared__ float sm[BM*LDE];
    float* sA = sm;                 // [BM][LDA]
    float* sB = sm + BM*LDA;        // [BK][LDB]

    const int tid  = threadIdx.x;
    const int warp = tid >> 5;
    const int wy   = warp / WCOLS;   // warp row
    const int wx   = warp % WCOLS;   // warp col
    const int row0 = blockIdx.y * BM;
    const int col0 = blockIdx.x * BN;

    wmma::fragment<wmma::accumulator, 16,16,8, float> acc[2][2];
    #pragma unroll
    for (int i = 0; i < 2; i++)
        #pragma unroll
        for (int j = 0; j < 2; j++) wmma::fill_fragment(acc[i][j], 0.0f);

    for (int k0 = 0; k0 < K; k0 += BK) {
        // stage A tile (BM x BK)
        #pragma unroll
        for (int f = tid; f < BM*(BK/4); f += NT) {
            int m  = f / (BK/4);
            int kq = (f % (BK/4)) * 4;
            float4 v = *reinterpret_cast<const float4*>(A + (size_t)(row0+m)*K + k0 + kq);
            float* d = &sA[m*LDA + kq];
            d[0] = wmma::__float_to_tf32(v.x);
            d[1] = wmma::__float_to_tf32(v.y);
            d[2] = wmma::__float_to_tf32(v.z);
            d[3] = wmma::__float_to_tf32(v.w);
        }
        // stage W tile (BK x BN), N-guarded
        #pragma unroll
        for (int f = tid; f < BK*(BN/4); f += NT) {
            int kr = f / (BN/4);
            int ng = (f % (BN/4)) * 4;
            int col = col0 + ng;
            float4 v;
            if (col + 3 < N) {
                v = *reinterpret_cast<const float4*>(W + (size_t)(k0+kr)*N + col);
            } else {
                v.x = (col+0 < N) ? W[(size_t)(k0+kr)*N + col+0] : 0.0f;
                v.y = (col+1 < N) ? W[(size_t)(k0+kr)*N + col+1] : 0.0f;
                v.z = (col+2 < N) ? W[(size_t)(k0+kr)*N + col+2] : 0.0f;
                v.w = (col+3 < N) ? W[(size_t)(k0+kr)*N + col+3] : 0.0f;
            }
            float* d = &sB[kr*LDB + ng];
            d[0] = wmma::__float_to_tf32(v.x);
            d[1] = wmma::__float_to_tf32(v.y);
            d[2] = wmma::__float_to_tf32(v.z);
            d[3] = wmma::__float_to_tf32(v.w);
        }
        __syncthreads();
        #pragma unroll
        for (int kk = 0; kk < BK/8; kk++) {
            wmma::fragment<wmma::matrix_a, 16,16,8, wmma::precision::tf32, wmma::row_major> af[2];
            wmma::fragment<wmma::matrix_b, 16,16,8, wmma::precision::tf32, wmma::row_major> bf[2];
            #pragma unroll
            for (int i = 0; i < 2; i++)
                wmma::load_matrix_sync(af[i], &sA[(wy*32 + i*16)*LDA + kk*8], LDA);
            #pragma unroll
            for (int j = 0; j < 2; j++)
                wmma::load_matrix_sync(bf[j], &sB[(kk*8)*LDB + wx*32 + j*16], LDB);
            #pragma unroll
            for (int i = 0; i < 2; i++)
                #pragma unroll
                for (int j = 0; j < 2; j++)
                    wmma::mma_sync(acc[i][j], af[i], bf[j], acc[i][j]);
        }
        __syncthreads();
    }

    // epilogue via smem (reuses sm), guarded + optional accumulate
    #pragma unroll
    for (int i = 0; i < 2; i++)
        #pragma unroll
        for (int j = 0; j < 2; j++)
            wmma::store_matrix_sync(&sm[(wy*32 + i*16)*LDE + wx*32 + j*16],
                                    acc[i][j], LDE, wmma::mem_row_major);
    __syncthreads();
    #pragma unroll
    for (int f = tid; f < BM*(BN/4); f += NT) {
        int r  = f / (BN/4);
        int cg = (f % (BN/4)) * 4;
        int gr = row0 + r;
        int gc = col0 + cg;
        if (gc + 3 < N) {
            float4 v = *reinterpret_cast<const float4*>(&sm[r*LDE + cg]);
            size_t idx = (size_t)gr*N + gc;
            if (accum) {
                float4 o = *reinterpret_cast<const float4*>(&C[idx]);
                v.x += o.x; v.y += o.y; v.z += o.z; v.w += o.w;
            }
            *reinterpret_cast<float4*>(&C[idx]) = v;
        } else {
            for (int q = 0; q < 4; q++) {
                int cc = gc + q;
                if (cc < N) {
                    float v = sm[r*LDE + cg + q];
                    size_t idx = (size_t)gr*N + cc;
                    if (accum) v += C[idx];
                    C[idx] = v;
                }
            }
        }
    }
}

// ---------------- depthwise causal conv (DC=4) + bias + silu ----------------
__global__ void k_conv(const float* __restrict__ w, const float* __restrict__ cb)
{
    int idx = blockIdx.x*256 + threadIdx.x;         // BL*ED
    if (idx >= BL*EDD) return;
    int e  = idx % EDD;
    int bl = idx / EDD;
    int l  = bl % LL;
    float4 wv = *reinterpret_cast<const float4*>(w + (size_t)e*DCC);
    const float* base = g_xz + (size_t)bl*(2*EDD) + e;   // xs_raw = xz[..., :ED]
    float acc = cb[e] + wv.w * base[0];
    if (l >= 1) acc += wv.z * base[-1*(2*EDD)];
    if (l >= 2) acc += wv.y * base[-2*(2*EDD)];
    if (l >= 3) acc += wv.x * base[-3*(2*EDD)];
    float sg = 1.0f/(1.0f + __expf(-acc));
    g_xs[idx] = acc * sg;                                // silu
}

// ---------------- delta: raw = xd[:,:16]@dt_w + dt_b; r=exp(-softplus), p=softplus*xs ----------------
__global__ void k_dlt(const float* __restrict__ dtw, const float* __restrict__ dtb)
{
    int idx = blockIdx.x*256 + threadIdx.x;         // BL*ED
    if (idx >= BL*EDD) return;
    int e  = idx % EDD;
    int bl = idx / EDD;
    const float* xr = g_xd + (size_t)bl*48;
    float acc = dtb[e];
    #pragma unroll
    for (int k = 0; k < RKK; k++)
        acc = fmaf(xr[k], dtw[(size_t)k*EDD + e], acc);
    float dlt, rr;
    if (acc > 15.0f) {
        dlt = acc;
        rr  = __expf(-acc);
    } else {
        float ex = __expf(acc);
        rr  = 1.0f/(1.0f + ex);
        dlt = log1pf(ex);
    }
    g_r[idx] = rr;
    g_p[idx] = dlt * g_xs[idx];
}

// ---------------- scan pass 1: per-chunk summaries (aP, bLoc) ----------------
__global__ void k_scan1(const float* __restrict__ Alog)
{
    int e = blockIdx.x*128 + threadIdx.x;
    int c = blockIdx.y, b = blockIdx.z;
    __shared__ float Bsh[CHL][NSS];
    for (int f = threadIdx.x; f < CHL*NSS; f += 128) {
        int t = f / NSS, n = f % NSS;
        Bsh[t][n] = g_xd[((size_t)(b*LL + c*CHL + t))*48 + RKK + n];
    }
    float a[NSS];
    bool fast = true;
    #pragma unroll
    for (int n = 0; n < NSS; n++) {
        a[n] = expf(Alog[(size_t)e*NSS + n]);
        if (fabsf(a[n] - (float)(n+1)) > 1e-4f*(float)(n+1)) fast = false;
    }
    __syncthreads();
    float h[NSS];
    #pragma unroll
    for (int n = 0; n < NSS; n++) h[n] = 0.0f;
    const float* rp = g_r + ((size_t)(b*LL + c*CHL))*EDD + e;
    const float* pp = g_p + ((size_t)(b*LL + c*CHL))*EDD + e;
    size_t ob = ((size_t)(b*NCH + c)*NSS)*EDD + e;
    if (fast) {
        float rprod = 1.0f;
        for (int t = 0; t < CHL; t++) {
            float rv = rp[(size_t)t*EDD], pv = pp[(size_t)t*EDD];
            float rn = 1.0f;
            #pragma unroll
            for (int n = 0; n < NSS; n++) {
                rn *= rv;
                h[n] = fmaf(rn, h[n], pv*Bsh[t][n]);
            }
            rprod *= rv;
        }
        float rpn = 1.0f;
        #pragma unroll
        for (int n = 0; n < NSS; n++) {
            rpn *= rprod;
            g_aP[ob + (size_t)n*EDD] = rpn;
            g_bL[ob + (size_t)n*EDD] = h[n];
        }
    } else {
        float msum = 0.0f;
        for (int t = 0; t < CHL; t++) {
            float rv = rp[(size_t)t*EDD], pv = pp[(size_t)t*EDD];
            float ml = __logf(rv);
            msum += ml;
            #pragma unroll
            for (int n = 0; n < NSS; n++) {
                float dA = __expf(a[n]*ml);
                h[n] = fmaf(dA, h[n], pv*Bsh[t][n]);
            }
        }
        #pragma unroll
        for (int n = 0; n < NSS; n++) {
            g_aP[ob + (size_t)n*EDD] = __expf(a[n]*msum);
            g_bL[ob + (size_t)n*EDD] = h[n];
        }
    }
}

// ---------------- scan pass 2: sequential combine over chunks -> initial states ----------------
__global__ void k_scan2()
{
    int idx = blockIdx.x*256 + threadIdx.x;   // BB*ED
    if (idx >= BB*EDD) return;
    int e = idx % EDD, b = idx / EDD;
    float h[NSS];
    #pragma unroll
    for (int n = 0; n < NSS; n++) h[n] = 0.0f;
    for (int c = 0; c < NCH; c++) {
        size_t ob = ((size_t)(b*NCH + c)*NSS)*EDD + e;
        #pragma unroll
        for (int n = 0; n < NSS; n++) {
            g_hI[ob + (size_t)n*EDD] = h[n];
            h[n] = fmaf(g_aP[ob + (size_t)n*EDD], h[n], g_bL[ob + (size_t)n*EDD]);
        }
    }
}

// ---------------- scan pass 3: replay with init state, emit y ----------------
__global__ void k_scan3(const float* __restrict__ Alog, const float* __restrict__ Dp)
{
    int e = blockIdx.x*128 + threadIdx.x;
    int c = blockIdx.y, b = blockIdx.z;
    __shared__ float Bsh[CHL][NSS];
    __shared__ float Csh[CHL][NSS];
    for (int f = threadIdx.x; f < CHL*NSS; f += 128) {
        int t = f / NSS, n = f % NSS;
        size_t rbase = ((size_t)(b*LL + c*CHL + t))*48;
        Bsh[t][n] = g_xd[rbase + RKK + n];
        Csh[t][n] = g_xd[rbase + RKK + NSS + n];
    }
    float a[NSS];
    bool fast = true;
    #pragma unroll
    for (int n = 0; n < NSS; n++) {
        a[n] = expf(Alog[(size_t)e*NSS + n]);
        if (fabsf(a[n] - (float)(n+1)) > 1e-4f*(float)(n+1)) fast = false;
    }
    __syncthreads();
    float h[NSS];
    size_t ob = ((size_t)(b*NCH + c)*NSS)*EDD + e;
    #pragma unroll
    for (int n = 0; n < NSS; n++) h[n] = g_hI[ob + (size_t)n*EDD];
    float dp = Dp[e];
    const float* rp = g_r  + ((size_t)(b*LL + c*CHL))*EDD + e;
    const float* pp = g_p  + ((size_t)(b*LL + c*CHL))*EDD + e;
    const float* xp = g_xs + ((size_t)(b*LL + c*CHL))*EDD + e;
    const float* zp = g_xz + ((size_t)(b*LL + c*CHL))*(2*EDD) + EDD + e;
    float*       yp = g_y  + ((size_t)(b*LL + c*CHL))*EDD + e;
    if (fast) {
        for (int t = 0; t < CHL; t++) {
            float rv = rp[(size_t)t*EDD], pv = pp[(size_t)t*EDD];
            float xv = xp[(size_t)t*EDD], zv = zp[(size_t)t*(2*EDD)];
            float yacc = dp * xv;
            float rn = 1.0f;
            #pragma unroll
            for (int n = 0; n < NSS; n++) {
                rn *= rv;
                h[n]  = fmaf(rn, h[n], pv*Bsh[t][n]);
                yacc  = fmaf(h[n], Csh[t][n], yacc);
            }
            float sg = 1.0f/(1.0f + __expf(-zv));
            yp[(size_t)t*EDD] = yacc * (zv * sg);
        }
    } else {
        for (int t = 0; t < CHL; t++) {
            float rv = rp[(size_t)t*EDD], pv = pp[(size_t)t*EDD];
            float xv = xp[(size_t)t*EDD], zv = zp[(size_t)t*(2*EDD)];
            float ml = __logf(rv);
            float yacc = dp * xv;
            #pragma unroll
            for (int n = 0; n < NSS; n++) {
                float dA = __expf(a[n]*ml);
                h[n]  = fmaf(dA, h[n], pv*Bsh[t][n]);
                yacc  = fmaf(h[n], Csh[t][n], yacc);
            }
            float sg = 1.0f/(1.0f + __expf(-zv));
            yp[(size_t)t*EDD] = yacc * (zv * sg);
        }
    }
}

// ---------------- head: out = LN(x)@hw + hb ----------------
__global__ void k_head(const float* __restrict__ hw, const float* __restrict__ hb,
                       float* __restrict__ out)
{
    int row = blockIdx.x, tid = threadIdx.x;   // 256 thr
    float v = g_xn[(size_t)row*DMD + tid];
    float p0 = v * hw[tid*QQ + 0];
    float p1 = v * hw[tid*QQ + 1];
    __shared__ float r0[8], r1[8];
    #pragma unroll
    for (int o = 16; o; o >>= 1) {
        p0 += __shfl_xor_sync(0xffffffffu, p0, o);
        p1 += __shfl_xor_sync(0xffffffffu, p1, o);
    }
    if ((tid & 31) == 0) { r0[tid>>5] = p0; r1[tid>>5] = p1; }
    __syncthreads();
    if (tid == 0) {
        float s0 = r0[0]+r0[1]+r0[2]+r0[3]+r0[4]+r0[5]+r0[6]+r0[7];
        float s1 = r1[0]+r1[1]+r1[2]+r1[3]+r1[4]+r1[5]+r1[6]+r1[7];
        out[(size_t)row*QQ + 0] = s0 + hb[0];
        out[(size_t)row*QQ + 1] = s1 + hb[1];
    }
}

// ---------------- launcher ----------------
extern "C" void kernel_launch(void* const* d_in, const int* in_sizes, int n_in,
                              void* d_out, int out_size)
{
    const int*   tokens    = (const int*)  d_in[0];
    const float* T         = (const float*)d_in[1];
    const float* tok_embed = (const float*)d_in[2];
    const float* pos_embed = (const float*)d_in[3];
    const float* tw1       = (const float*)d_in[4];
    const float* tb1       = (const float*)d_in[5];
    const float* tw2       = (const float*)d_in[6];
    const float* tb2       = (const float*)d_in[7];
    const float* ag        = (const float*)d_in[8];
    const float* ab        = (const float*)d_in[9];
    const float* apw       = (const float*)d_in[10];
    const float* apb       = (const float*)d_in[11];
    const float* in_w      = (const float*)d_in[12];
    const float* conv_w    = (const float*)d_in[13];
    const float* conv_b    = (const float*)d_in[14];
    const float* xp_w      = (const float*)d_in[15];
    const float* dt_w      = (const float*)d_in[16];
    const float* dt_b      = (const float*)d_in[17];
    const float* A_log     = (const float*)d_in[18];
    const float* Dp        = (const float*)d_in[19];
    const float* out_w     = (const float*)d_in[20];
    const float* fg        = (const float*)d_in[21];
    const float* fb        = (const float*)d_in[22];
    const float* hw        = (const float*)d_in[23];
    const float* hb        = (const float*)d_in[24];
    float* out = (float*)d_out;

    float *px, *pxn, *pxz, *pxs, *py, *pxd, *pss;
    cudaGetSymbolAddress((void**)&px,  g_x);
    cudaGetSymbolAddress((void**)&pxn, g_xn);
    cudaGetSymbolAddress((void**)&pxz, g_xz);
    cudaGetSymbolAddress((void**)&pxs, g_xs);
    cudaGetSymbolAddress((void**)&py,  g_y);
    cudaGetSymbolAddress((void**)&pxd, g_xd);
    cudaGetSymbolAddress((void**)&pss, g_ss);

    k_embed<<<(BL*DMD + 255)/256, 256>>>(tokens, tok_embed, pos_embed);
    k_cond<<<1, BB*CDD>>>(T, tw1, tb1, tw2, tb2);
    k_ss<<<(NLY*BB*2*DMD + 255)/256, 256>>>(apw, apb);

    for (int i = 0; i < NLY; i++) {
        // AdaLN
        k_ln<<<BL, DMD>>>(px, ag + (size_t)i*DMD, ab + (size_t)i*DMD,
                          pss + (size_t)i*BB*2*DMD, pxn);
        // xz = xn @ in_w[i]   (8192 x 1024, K=256)  [tensor cores]
        gemm_tf32<128,64,16><<<dim3(2*EDD/64, BL/128), 256>>>(
            pxn, in_w + (size_t)i*DMD*2*EDD, pxz, BL, 2*EDD, DMD, 0);
        // causal depthwise conv + silu
        k_conv<<<(BL*EDD + 255)/256, 256>>>(conv_w + (size_t)i*EDD*DCC,
                                            conv_b + (size_t)i*EDD);
        // xd = xs @ xp_w[i]   (8192 x 48, K=512)  [tensor cores]
        gemm_tf32<64,64,16><<<dim3(1, BL/64), 128>>>(
            pxs, xp_w + (size_t)i*EDD*(RKK+2*NSS), pxd, BL, RKK+2*NSS, EDD, 0);
        // delta -> r, p
        k_dlt<<<(BL*EDD + 255)/256, 256>>>(dt_w + (size_t)i*RKK*EDD,
                                           dt_b + (size_t)i*EDD);
        // chunked selective scan
        k_scan1<<<dim3(EDD/128, NCH, BB), 128>>>(A_log + (size_t)i*EDD*NSS);
        k_scan2<<<(BB*EDD + 255)/256, 256>>>();
        k_scan3<<<dim3(EDD/128, NCH, BB), 128>>>(A_log + (size_t)i*EDD*NSS,
                                                 Dp + (size_t)i*EDD);
        // x += y @ out_w[i]   (8192 x 256, K=512), accumulate  [tensor cores]
        gemm_tf32<128,64,16><<<dim3(DMD/64, BL/128), 256>>>(
            py, out_w + (size_t)i*EDD*DMD, px, BL, DMD, EDD, 1);
    }

    // final LN + head
    k_ln<<<BL, DMD>>>(px, fg, fb, nullptr, pxn);
    k_head<<<BL, 256>>>(hw, hb, out);
}

// round 5
// speedup vs baseline: 1.2915x; 1.1395x over previous
#include <cuda_runtime.h>
#include <mma.h>
#include <math.h>
#include <stdint.h>

using namespace nvcuda;

// ---------------- problem constants ----------------
#define BB   8
#define LL   1024
#define DMD  256
#define NLY  4
#define EDD  512
#define NSS  16
#define DCC  4
#define RKK  16
#define CDD  64
#define QQ   2
#define BL   (BB*LL)          // 8192 rows
#define NCH  16               // scan chunks
#define CHL  (LL/NCH)         // 64 steps per chunk
#define XDS  64               // padded row stride of xd buffer (48 -> 64)

// ---------------- scratch (static device globals; no allocs allowed) ----------------
__device__ __align__(256) float g_x [BL*DMD];
__device__ __align__(256) float g_xn[BL*DMD];
__device__ __align__(256) float g_xz[BL*2*EDD];
__device__ __align__(256) float g_xs[BL*EDD];
__device__ __align__(256) float g_r [BL*EDD];
__device__ __align__(256) float g_p [BL*EDD];
__device__ __align__(256) float g_y [BL*EDD];
__device__ __align__(256) float g_xd[BL*XDS];
__device__ __align__(256) float g_cond[BB*CDD];
__device__ __align__(256) float g_ss[NLY*BB*2*DMD];
__device__ __align__(256) float g_aP[BB*NCH*NSS*EDD];
__device__ __align__(256) float g_bL[BB*NCH*NSS*EDD];
__device__ __align__(256) float g_hI[BB*NCH*NSS*EDD];

// ---------------- cp.async helpers ----------------
__device__ __forceinline__ void cp16(void* smem_dst, const void* gsrc, int src_bytes)
{
    uint32_t d = (uint32_t)__cvta_generic_to_shared(smem_dst);
    asm volatile("cp.async.cg.shared.global [%0], [%1], 16, %2;\n"
                 :: "r"(d), "l"(gsrc), "r"(src_bytes));
}
__device__ __forceinline__ void cp_commit() { asm volatile("cp.async.commit_group;\n"); }
template<int NG> __device__ __forceinline__ void cp_wait()
{ asm volatile("cp.async.wait_group %0;\n" :: "n"(NG)); }

// ---------------- embed: x = shift(tok_embed[tokens]) + pos_embed ----------------
__global__ void k_embed(const int* __restrict__ tokens,
                        const float* __restrict__ tok_embed,
                        const float* __restrict__ pos_embed)
{
    int idx = blockIdx.x * 256 + threadIdx.x;
    if (idx >= BL*DMD) return;
    int d  = idx % DMD;
    int bl = idx / DMD;
    int l  = bl % LL;
    int b  = bl / LL;
    float v = pos_embed[l*DMD + d];
    if (l > 0) {
        int tok = tokens[b*LL + l - 1];
        v += tok_embed[tok*DMD + d];
    }
    g_x[idx] = v;
}

// ---------------- conditioning (tiny) ----------------
__global__ void k_cond(const float* __restrict__ T,  const float* __restrict__ tw1,
                       const float* __restrict__ tb1,const float* __restrict__ tw2,
                       const float* __restrict__ tb2)
{
    __shared__ float hs[BB*CDD];
    int tid = threadIdx.x;            // 512 threads
    int b = tid / CDD, c = tid % CDD;
    float u = T[b]*tw1[c] + tb1[c];
    float g = 0.5f*u*(1.0f + erff(u*0.70710678118654752440f));
    hs[b*CDD + c] = g;
    __syncthreads();
    float acc = tb2[c];
    #pragma unroll 8
    for (int k = 0; k < CDD; k++) acc += hs[b*CDD + k]*tw2[k*CDD + c];
    g_cond[b*CDD + c] = acc;
}

// ---------------- per-layer modulation vectors ----------------
__global__ void k_ss(const float* __restrict__ apw, const float* __restrict__ apb)
{
    int idx = blockIdx.x*256 + threadIdx.x;     // NLY*BB*2DM = 16384
    if (idx >= NLY*BB*2*DMD) return;
    int j  = idx % (2*DMD);
    int ib = idx / (2*DMD);
    int b  = ib % BB;
    int i  = ib / BB;
    float acc = apb[i*2*DMD + j];
    #pragma unroll 8
    for (int c = 0; c < CDD; c++)
        acc += g_cond[b*CDD + c] * apw[((size_t)i*CDD + c)*2*DMD + j];
    g_ss[((size_t)i*BB + b)*2*DMD + j] = acc;
}

// ---------------- LayerNorm (+AdaLN), vectorized: 64 thr x float4 per row, 4 rows/block ----------------
__global__ void k_ln(const float* __restrict__ x, const float* __restrict__ gam,
                     const float* __restrict__ bet, const float* __restrict__ ss,
                     float* __restrict__ out)
{
    int tid = threadIdx.x;              // 256
    int rl  = tid >> 6;                 // row in block 0..3
    int lw  = tid & 63;                 // lane in row
    int row = blockIdx.x*4 + rl;
    float4 v = reinterpret_cast<const float4*>(x + (size_t)row*DMD)[lw];
    float s  = v.x+v.y+v.z+v.w;
    float s2 = v.x*v.x+v.y*v.y+v.z*v.z+v.w*v.w;
    #pragma unroll
    for (int o = 16; o; o >>= 1) {
        s  += __shfl_xor_sync(0xffffffffu, s,  o);
        s2 += __shfl_xor_sync(0xffffffffu, s2, o);
    }
    __shared__ float sh1[4][2], sh2[4][2];
    if ((lw & 31) == 0) { sh1[rl][lw>>5] = s; sh2[rl][lw>>5] = s2; }
    __syncthreads();
    float tot  = sh1[rl][0] + sh1[rl][1];
    float tot2 = sh2[rl][0] + sh2[rl][1];
    float mean = tot * (1.0f/DMD);
    float var  = tot2 * (1.0f/DMD) - mean*mean;
    float inv  = rsqrtf(var + 1e-5f);
    float4 g  = reinterpret_cast<const float4*>(gam)[lw];
    float4 bb = reinterpret_cast<const float4*>(bet)[lw];
    float4 o4;
    o4.x = (v.x-mean)*inv*g.x + bb.x;
    o4.y = (v.y-mean)*inv*g.y + bb.y;
    o4.z = (v.z-mean)*inv*g.z + bb.z;
    o4.w = (v.w-mean)*inv*g.w + bb.w;
    if (ss) {
        int b = row / LL;
        float4 sc = reinterpret_cast<const float4*>(ss + (size_t)b*2*DMD)[lw];
        float4 sh = reinterpret_cast<const float4*>(ss + (size_t)b*2*DMD + DMD)[lw];
        o4.x = fmaf(sc.x, o4.x, o4.x) + sh.x;
        o4.y = fmaf(sc.y, o4.y, o4.y) + sh.y;
        o4.z = fmaf(sc.z, o4.z, o4.z) + sh.z;
        o4.w = fmaf(sc.w, o4.w, o4.w) + sh.w;
    }
    reinterpret_cast<float4*>(out + (size_t)row*DMD)[lw] = o4;
}

// ---------------- pipelined TF32 GEMM: C[M,ldc] (+)= A[M,K] @ W[K,Nw] ----------------
// Double-buffered cp.async, WRxWC warps with (BM/WR)x(BN/WC) warp tiles.
// B cols >= Nw are zero-filled; stores are unguarded over BN (ldc must cover col0+BN).
template<int BM, int BN, int BK, int WR, int WC>
__global__ void __launch_bounds__(WR*WC*32)
gemm_tf32p(const float* __restrict__ A, const float* __restrict__ W,
           float* __restrict__ C, int M, int Nw, int K, int ldc, int accum)
{
    constexpr int NT  = WR*WC*32;
    constexpr int WM  = BM/WR, WN = BN/WC;
    constexpr int MI  = WM/16, NI = WN/16;
    constexpr int LDA = BK + 4;
    constexpr int LDB = BN + 4;
    extern __shared__ float sm[];
    float* sA = sm;                       // [2][BM][LDA]
    float* sB = sm + 2*BM*LDA;            // [2][BK][LDB]

    const int tid  = threadIdx.x;
    const int warp = tid >> 5;
    const int wy   = warp / WC;
    const int wx   = warp % WC;
    const int row0 = blockIdx.y * BM;
    const int col0 = blockIdx.x * BN;

    wmma::fragment<wmma::accumulator, 16,16,8, float> acc[MI][NI];
    #pragma unroll
    for (int i = 0; i < MI; i++)
        #pragma unroll
        for (int j = 0; j < NI; j++) wmma::fill_fragment(acc[i][j], 0.0f);

    auto load_tiles = [&](int st, int k0) {
        float* dA = sA + st*BM*LDA;
        float* dB = sB + st*BK*LDB;
        #pragma unroll
        for (int f = tid; f < BM*(BK/4); f += NT) {
            int r = f / (BK/4);
            int c = (f % (BK/4)) * 4;
            cp16(&dA[r*LDA + c], A + (size_t)(row0+r)*K + k0 + c, 16);
        }
        #pragma unroll
        for (int f = tid; f < BK*(BN/4); f += NT) {
            int r = f / (BN/4);
            int c = (f % (BN/4)) * 4;
            int col = col0 + c;
            int sb  = (col < Nw) ? 16 : 0;
            const float* src = W + (size_t)(k0+r)*Nw + (sb ? col : 0);
            cp16(&dB[r*LDB + c], src, sb);
        }
    };

    const int nt = K / BK;
    int stage = 0;
    load_tiles(0, 0);
    cp_commit();

    for (int t = 0; t < nt; t++) {
        if (t + 1 < nt) {
            load_tiles(stage ^ 1, (t+1)*BK);
            cp_commit();
            cp_wait<1>();
        } else {
            cp_wait<0>();
        }
        __syncthreads();
        const float* cA = sA + stage*BM*LDA;
        const float* cB = sB + stage*BK*LDB;
        #pragma unroll
        for (int kk = 0; kk < BK/8; kk++) {
            wmma::fragment<wmma::matrix_a, 16,16,8, wmma::precision::tf32, wmma::row_major> af[MI];
            wmma::fragment<wmma::matrix_b, 16,16,8, wmma::precision::tf32, wmma::row_major> bf[NI];
            #pragma unroll
            for (int i = 0; i < MI; i++)
                wmma::load_matrix_sync(af[i], &cA[(wy*WM + i*16)*LDA + kk*8], LDA);
            #pragma unroll
            for (int j = 0; j < NI; j++)
                wmma::load_matrix_sync(bf[j], &cB[(kk*8)*LDB + wx*WN + j*16], LDB);
            #pragma unroll
            for (int i = 0; i < MI; i++)
                #pragma unroll
                for (int j = 0; j < NI; j++)
                    wmma::mma_sync(acc[i][j], af[i], bf[j], acc[i][j]);
        }
        __syncthreads();
        stage ^= 1;
    }

    // direct fragment epilogue (unguarded; ldc covers col0+BN)
    #pragma unroll
    for (int i = 0; i < MI; i++) {
        #pragma unroll
        for (int j = 0; j < NI; j++) {
            float* cptr = C + (size_t)(row0 + wy*WM + i*16)*ldc + col0 + wx*WN + j*16;
            if (accum) {
                wmma::fragment<wmma::accumulator, 16,16,8, float> o;
                wmma::load_matrix_sync(o, cptr, ldc, wmma::mem_row_major);
                #pragma unroll
                for (int e = 0; e < o.num_elements; e++) acc[i][j].x[e] += o.x[e];
            }
            wmma::store_matrix_sync(cptr, acc[i][j], ldc, wmma::mem_row_major);
        }
    }
}

// ---------------- depthwise causal conv (DC=4) + bias + silu ----------------
__global__ void k_conv(const float* __restrict__ w, const float* __restrict__ cb)
{
    int idx = blockIdx.x*256 + threadIdx.x;         // BL*ED
    if (idx >= BL*EDD) return;
    int e  = idx % EDD;
    int bl = idx / EDD;
    int l  = bl % LL;
    float4 wv = *reinterpret_cast<const float4*>(w + (size_t)e*DCC);
    const float* base = g_xz + (size_t)bl*(2*EDD) + e;   // xs_raw = xz[..., :ED]
    float acc = cb[e] + wv.w * base[0];
    if (l >= 1) acc += wv.z * base[-1*(2*EDD)];
    if (l >= 2) acc += wv.y * base[-2*(2*EDD)];
    if (l >= 3) acc += wv.x * base[-3*(2*EDD)];
    float sg = 1.0f/(1.0f + __expf(-acc));
    g_xs[idx] = acc * sg;                                // silu
}

// ---------------- delta: raw = xd[:,:16]@dt_w + dt_b; r=exp(-softplus), p=softplus*xs ----------------
__global__ void k_dlt(const float* __restrict__ dtw, const float* __restrict__ dtb)
{
    int idx = blockIdx.x*256 + threadIdx.x;         // BL*ED
    if (idx >= BL*EDD) return;
    int e  = idx % EDD;
    int bl = idx / EDD;
    const float* xr = g_xd + (size_t)bl*XDS;
    float acc = dtb[e];
    #pragma unroll
    for (int k = 0; k < RKK; k++)
        acc = fmaf(xr[k], dtw[(size_t)k*EDD + e], acc);
    float dlt, rr;
    if (acc > 15.0f) {
        dlt = acc;
        rr  = __expf(-acc);
    } else {
        float ex = __expf(acc);
        rr  = 1.0f/(1.0f + ex);
        dlt = log1pf(ex);
    }
    g_r[idx] = rr;
    g_p[idx] = dlt * g_xs[idx];
}

// ---------------- scan pass 1: per-chunk summaries ----------------
__global__ void k_scan1(const float* __restrict__ Alog)
{
    int e = blockIdx.x*128 + threadIdx.x;
    int c = blockIdx.y, b = blockIdx.z;
    __shared__ float Bsh[CHL][NSS];
    for (int f = threadIdx.x; f < CHL*NSS; f += 128) {
        int t = f / NSS, n = f % NSS;
        Bsh[t][n] = g_xd[((size_t)(b*LL + c*CHL + t))*XDS + RKK + n];
    }
    float a[NSS];
    bool fast = true;
    #pragma unroll
    for (int n = 0; n < NSS; n++) {
        a[n] = expf(Alog[(size_t)e*NSS + n]);
        if (fabsf(a[n] - (float)(n+1)) > 1e-4f*(float)(n+1)) fast = false;
    }
    __syncthreads();
    float h[NSS];
    #pragma unroll
    for (int n = 0; n < NSS; n++) h[n] = 0.0f;
    const float* rp = g_r + ((size_t)(b*LL + c*CHL))*EDD + e;
    const float* pp = g_p + ((size_t)(b*LL + c*CHL))*EDD + e;
    size_t ob = ((size_t)(b*NCH + c)*NSS)*EDD + e;
    if (fast) {
        float rprod = 1.0f;
        for (int t = 0; t < CHL; t++) {
            float rv = rp[(size_t)t*EDD], pv = pp[(size_t)t*EDD];
            float rn = 1.0f;
            #pragma unroll
            for (int n = 0; n < NSS; n++) {
                rn *= rv;
                h[n] = fmaf(rn, h[n], pv*Bsh[t][n]);
            }
            rprod *= rv;
        }
        float rpn = 1.0f;
        #pragma unroll
        for (int n = 0; n < NSS; n++) {
            rpn *= rprod;
            g_aP[ob + (size_t)n*EDD] = rpn;
            g_bL[ob + (size_t)n*EDD] = h[n];
        }
    } else {
        float msum = 0.0f;
        for (int t = 0; t < CHL; t++) {
            float rv = rp[(size_t)t*EDD], pv = pp[(size_t)t*EDD];
            float ml = __logf(rv);
            msum += ml;
            #pragma unroll
            for (int n = 0; n < NSS; n++) {
                float dA = __expf(a[n]*ml);
                h[n] = fmaf(dA, h[n], pv*Bsh[t][n]);
            }
        }
        #pragma unroll
        for (int n = 0; n < NSS; n++) {
            g_aP[ob + (size_t)n*EDD] = __expf(a[n]*msum);
            g_bL[ob + (size_t)n*EDD] = h[n];
        }
    }
}

// ---------------- scan pass 2 ----------------
__global__ void k_scan2()
{
    int idx = blockIdx.x*256 + threadIdx.x;   // BB*ED
    if (idx >= BB*EDD) return;
    int e = idx % EDD, b = idx / EDD;
    float h[NSS];
    #pragma unroll
    for (int n = 0; n < NSS; n++) h[n] = 0.0f;
    for (int c = 0; c < NCH; c++) {
        size_t ob = ((size_t)(b*NCH + c)*NSS)*EDD + e;
        #pragma unroll
        for (int n = 0; n < NSS; n++) {
            g_hI[ob + (size_t)n*EDD] = h[n];
            h[n] = fmaf(g_aP[ob + (size_t)n*EDD], h[n], g_bL[ob + (size_t)n*EDD]);
        }
    }
}

// ---------------- scan pass 3 ----------------
__global__ void k_scan3(const float* __restrict__ Alog, const float* __restrict__ Dp)
{
    int e = blockIdx.x*128 + threadIdx.x;
    int c = blockIdx.y, b = blockIdx.z;
    __shared__ float Bsh[CHL][NSS];
    __shared__ float Csh[CHL][NSS];
    for (int f = threadIdx.x; f < CHL*NSS; f += 128) {
        int t = f / NSS, n = f % NSS;
        size_t rbase = ((size_t)(b*LL + c*CHL + t))*XDS;
        Bsh[t][n] = g_xd[rbase + RKK + n];
        Csh[t][n] = g_xd[rbase + RKK + NSS + n];
    }
    float a[NSS];
    bool fast = true;
    #pragma unroll
    for (int n = 0; n < NSS; n++) {
        a[n] = expf(Alog[(size_t)e*NSS + n]);
        if (fabsf(a[n] - (float)(n+1)) > 1e-4f*(float)(n+1)) fast = false;
    }
    __syncthreads();
    float h[NSS];
    size_t ob = ((size_t)(b*NCH + c)*NSS)*EDD + e;
    #pragma unroll
    for (int n = 0; n < NSS; n++) h[n] = g_hI[ob + (size_t)n*EDD];
    float dp = Dp[e];
    const float* rp = g_r  + ((size_t)(b*LL + c*CHL))*EDD + e;
    const float* pp = g_p  + ((size_t)(b*LL + c*CHL))*EDD + e;
    const float* xp = g_xs + ((size_t)(b*LL + c*CHL))*EDD + e;
    const float* zp = g_xz + ((size_t)(b*LL + c*CHL))*(2*EDD) + EDD + e;
    float*       yp = g_y  + ((size_t)(b*LL + c*CHL))*EDD + e;
    if (fast) {
        for (int t = 0; t < CHL; t++) {
            float rv = rp[(size_t)t*EDD], pv = pp[(size_t)t*EDD];
            float xv = xp[(size_t)t*EDD], zv = zp[(size_t)t*(2*EDD)];
            float yacc = dp * xv;
            float rn = 1.0f;
            #pragma unroll
            for (int n = 0; n < NSS; n++) {
                rn *= rv;
                h[n]  = fmaf(rn, h[n], pv*Bsh[t][n]);
                yacc  = fmaf(h[n], Csh[t][n], yacc);
            }
            float sg = 1.0f/(1.0f + __expf(-zv));
            yp[(size_t)t*EDD] = yacc * (zv * sg);
        }
    } else {
        for (int t = 0; t < CHL; t++) {
            float rv = rp[(size_t)t*EDD], pv = pp[(size_t)t*EDD];
            float xv = xp[(size_t)t*EDD], zv = zp[(size_t)t*(2*EDD)];
            float ml = __logf(rv);
            float yacc = dp * xv;
            #pragma unroll
            for (int n = 0; n < NSS; n++) {
                float dA = __expf(a[n]*ml);
                h[n]  = fmaf(dA, h[n], pv*Bsh[t][n]);
                yacc  = fmaf(h[n], Csh[t][n], yacc);
            }
            float sg = 1.0f/(1.0f + __expf(-zv));
            yp[(size_t)t*EDD] = yacc * (zv * sg);
        }
    }
}

// ---------------- head: out = LN(x)@hw + hb ----------------
__global__ void k_head(const float* __restrict__ hw, const float* __restrict__ hb,
                       float* __restrict__ out)
{
    int row = blockIdx.x, tid = threadIdx.x;   // 256 thr
    float v = g_xn[(size_t)row*DMD + tid];
    float p0 = v * hw[tid*QQ + 0];
    float p1 = v * hw[tid*QQ + 1];
    __shared__ float r0[8], r1[8];
    #pragma unroll
    for (int o = 16; o; o >>= 1) {
        p0 += __shfl_xor_sync(0xffffffffu, p0, o);
        p1 += __shfl_xor_sync(0xffffffffu, p1, o);
    }
    if ((tid & 31) == 0) { r0[tid>>5] = p0; r1[tid>>5] = p1; }
    __syncthreads();
    if (tid == 0) {
        float s0 = r0[0]+r0[1]+r0[2]+r0[3]+r0[4]+r0[5]+r0[6]+r0[7];
        float s1 = r1[0]+r1[1]+r1[2]+r1[3]+r1[4]+r1[5]+r1[6]+r1[7];
        out[(size_t)row*QQ + 0] = s0 + hb[0];
        out[(size_t)row*QQ + 1] = s1 + hb[1];
    }
}

// ---------------- launcher ----------------
extern "C" void kernel_launch(void* const* d_in, const int* in_sizes, int n_in,
                              void* d_out, int out_size)
{
    const int*   tokens    = (const int*)  d_in[0];
    const float* T         = (const float*)d_in[1];
    const float* tok_embed = (const float*)d_in[2];
    const float* pos_embed = (const float*)d_in[3];
    const float* tw1       = (const float*)d_in[4];
    const float* tb1       = (const float*)d_in[5];
    const float* tw2       = (const float*)d_in[6];
    const float* tb2       = (const float*)d_in[7];
    const float* ag        = (const float*)d_in[8];
    const float* ab        = (const float*)d_in[9];
    const float* apw       = (const float*)d_in[10];
    const float* apb       = (const float*)d_in[11];
    const float* in_w      = (const float*)d_in[12];
    const float* conv_w    = (const float*)d_in[13];
    const float* conv_b    = (const float*)d_in[14];
    const float* xp_w      = (const float*)d_in[15];
    const float* dt_w      = (const float*)d_in[16];
    const float* dt_b      = (const float*)d_in[17];
    const float* A_log     = (const float*)d_in[18];
    const float* Dp        = (const float*)d_in[19];
    const float* out_w     = (const float*)d_in[20];
    const float* fg        = (const float*)d_in[21];
    const float* fb        = (const float*)d_in[22];
    const float* hw        = (const float*)d_in[23];
    const float* hb        = (const float*)d_in[24];
    float* out = (float*)d_out;

    float *px, *pxn, *pxz, *pxs, *py, *pxd, *pss;
    cudaGetSymbolAddress((void**)&px,  g_x);
    cudaGetSymbolAddress((void**)&pxn, g_xn);
    cudaGetSymbolAddress((void**)&pxz, g_xz);
    cudaGetSymbolAddress((void**)&pxs, g_xs);
    cudaGetSymbolAddress((void**)&py,  g_y);
    cudaGetSymbolAddress((void**)&pxd, g_xd);
    cudaGetSymbolAddress((void**)&pss, g_ss);

    // dynamic smem sizes for the pipelined GEMMs
    const int SM_BIG = (2*128*(32+4) + 2*32*(128+4)) * 4;   // 70656 B
    const int SM_SML = (2*64*(32+4)  + 2*32*(64+4))  * 4;   // 35840 B
    static bool attr_done = false;
    if (!attr_done) {
        cudaFuncSetAttribute((const void*)gemm_tf32p<128,128,32,2,4>,
                             cudaFuncAttributeMaxDynamicSharedMemorySize, SM_BIG);
        attr_done = true;
    }

    k_embed<<<(BL*DMD + 255)/256, 256>>>(tokens, tok_embed, pos_embed);
    k_cond<<<1, BB*CDD>>>(T, tw1, tb1, tw2, tb2);
    k_ss<<<(NLY*BB*2*DMD + 255)/256, 256>>>(apw, apb);

    for (int i = 0; i < NLY; i++) {
        // AdaLN
        k_ln<<<BL/4, 256>>>(px, ag + (size_t)i*DMD, ab + (size_t)i*DMD,
                            pss + (size_t)i*BB*2*DMD, pxn);
        // xz = xn @ in_w[i]   (8192x1024, K=256)
        gemm_tf32p<128,128,32,2,4><<<dim3(2*EDD/128, BL/128), 256, SM_BIG>>>(
            pxn, in_w + (size_t)i*DMD*2*EDD, pxz, BL, 2*EDD, DMD, 2*EDD, 0);
        // causal depthwise conv + silu
        k_conv<<<(BL*EDD + 255)/256, 256>>>(conv_w + (size_t)i*EDD*DCC,
                                            conv_b + (size_t)i*EDD);
        // xd = xs @ xp_w[i]   (8192x48 -> padded 64, K=512)
        gemm_tf32p<64,64,32,2,2><<<dim3(1, BL/64), 128, SM_SML>>>(
            pxs, xp_w + (size_t)i*EDD*(RKK+2*NSS), pxd, BL, RKK+2*NSS, EDD, XDS, 0);
        // delta -> r, p
        k_dlt<<<(BL*EDD + 255)/256, 256>>>(dt_w + (size_t)i*RKK*EDD,
                                           dt_b + (size_t)i*EDD);
        // chunked selective scan
        k_scan1<<<dim3(EDD/128, NCH, BB), 128>>>(A_log + (size_t)i*EDD*NSS);
        k_scan2<<<(BB*EDD + 255)/256, 256>>>();
        k_scan3<<<dim3(EDD/128, NCH, BB), 128>>>(A_log + (size_t)i*EDD*NSS,
                                                 Dp + (size_t)i*EDD);
        // x += y @ out_w[i]   (8192x256, K=512), accumulate
        gemm_tf32p<128,128,32,2,4><<<dim3(DMD/128, BL/128), 256, SM_BIG>>>(
            py, out_w + (size_t)i*EDD*DMD, px, BL, DMD, EDD, DMD, 1);
    }

    // final LN + head
    k_ln<<<BL/4, 256>>>(px, fg, fb, nullptr, pxn);
    k_head<<<BL, 256>>>(hw, hb, out);
}